// round 5
// baseline (speedup 1.0000x reference)
#include <cuda_runtime.h>
#include <cstdint>

// Shapes fixed by the reference: K=64, N=128, T=32768
#define KU   64
#define NU   128
#define EPSV 0.01f
#define INF_BITS 0x7F800000u

// Device-global state. The last retiring block restores these invariants at
// the end of every call, so graph replays stay deterministic.
__device__ unsigned int g_min_bits = INF_BITS;  // running min(mgn) as float bits
__device__ unsigned int g_need     = 0;         // 1 => some block saw min<=0 / slow path
__device__ unsigned int g_done     = 0;         // retired-block counter

__device__ __forceinline__ void atomic_min_float(float val) {
    if (val >= 0.0f) atomicMin((int*)&g_min_bits, __float_as_int(val));
    else             atomicMax(&g_min_bits, __float_as_uint(val));
}

// Retire with release semantics (orders all prior stores) and acquire
// semantics (covers the last block's subsequent reads). One RMW, no membars.
__device__ __forceinline__ unsigned retire_acq_rel(unsigned int* ctr) {
    unsigned prev;
    asm volatile("atom.acq_rel.gpu.global.add.u32 %0, [%1], 1;"
                 : "=r"(prev) : "l"(ctr) : "memory");
    return prev;
}

// ---------------------------------------------------------------------------
// Single fused kernel. 256 threads/block, one float4 of t per thread.
// Every block redundantly derives the cubic coefficients from W,b (parallel
// across blocks, so wall cost == one block's cost). Tail is minimal: threads
// 1..255 exit right after depositing their warp-min; thread 0 reduces,
// escalates only if the result could matter, and retires with one acq_rel RMW.
// ---------------------------------------------------------------------------
__global__ void __launch_bounds__(256)
fused_mgn_kernel(const float* __restrict__ t,
                 const float* __restrict__ W,
                 const float* __restrict__ b,
                 const float* __restrict__ V,
                 const float* __restrict__ a,
                 float* __restrict__ out,
                 int T, int vlen, int nblocks) {
    __shared__ float sc0[KU], sc1[KU], sc2[KU], sc3[KU];
    __shared__ float scoef[6];   // c0,c1,c2,c3,vsum,a
    __shared__ int   sneg;       // any W or b negative?
    __shared__ float swm[8];
    __shared__ int   sbad[8];

    const int tid  = threadIdx.x;
    const int T4   = T >> 2;
    const int tail = T - (T4 << 2);
    const int i4   = blockIdx.x * 256 + tid;

    if (tid == 0) sneg = 0;

    // ---- Hoisted t load: overlap its DRAM latency with the W/b loads ----
    float4 tv4 = make_float4(0.f, 0.f, 0.f, 0.f);
    const bool have_t = (i4 < T4);
    if (have_t) tv4 = __ldg(&((const float4*)t)[i4]);

    // ---- Phase 1: per-unit sums -> per-k cubic contributions ----
    {
        const int k = tid >> 2, quad = tid & 3;   // 4 threads per unit k
        const float4* W4 = (const float4*)W;
        const float4* B4 = (const float4*)b;
        float s2 = 0.f, sb = 0.f, bb = 0.f;
        bool  neg = false;
        #pragma unroll
        for (int j = 0; j < 8; ++j) {             // 8 float4 = 32 floats each
            const int idx = k * (NU/4) + quad * 8 + j;
            const float4 w  = __ldg(&W4[idx]);
            const float4 bv = __ldg(&B4[idx]);
            #pragma unroll
            for (int c = 0; c < 4; ++c) {
                const float wv = (&w.x)[c], bvv = (&bv.x)[c];
                s2 = fmaf(wv,  wv,  s2);
                sb = fmaf(wv,  bvv, sb);
                bb = fmaf(bvv, bvv, bb);
                neg |= (wv < 0.f) | (bvv < 0.f);
            }
        }
        #pragma unroll
        for (int off = 2; off; off >>= 1) {
            s2 += __shfl_down_sync(0xFFFFFFFFu, s2, off, 4);
            sb += __shfl_down_sync(0xFFFFFFFFu, sb, off, 4);
            bb += __shfl_down_sync(0xFFFFFFFFu, bb, off, 4);
        }
        const unsigned nb = __ballot_sync(0xFFFFFFFFu, neg);
        if ((tid & 31) == 0 && nb) sneg = 1;       // benign smem race, all write 1
        if (quad == 0) {
            sc3[k] = 0.5f * s2 * s2;
            sc2[k] = 1.5f * s2 * sb;
            sc1[k] = fmaf(sb, sb, 0.5f * bb * s2);
            sc0[k] = 0.5f * bb * sb;
        }
    }
    __syncthreads();

    // ---- Phase 2: reduce over k; vsum; a ----
    if (tid < 32) {                                // warp 0: sum 64 -> 1
        float c0 = sc0[tid] + sc0[tid + 32];
        float c1 = sc1[tid] + sc1[tid + 32];
        float c2 = sc2[tid] + sc2[tid + 32];
        float c3 = sc3[tid] + sc3[tid + 32];
        #pragma unroll
        for (int off = 16; off; off >>= 1) {
            c0 += __shfl_down_sync(0xFFFFFFFFu, c0, off);
            c1 += __shfl_down_sync(0xFFFFFFFFu, c1, off);
            c2 += __shfl_down_sync(0xFFFFFFFFu, c2, off);
            c3 += __shfl_down_sync(0xFFFFFFFFu, c3, off);
        }
        if (tid == 0) { scoef[0]=c0; scoef[1]=c1; scoef[2]=c2; scoef[3]=c3; }
    } else if (tid < 64) {                         // warp 1: vsum = sum(V*V)
        const int lid = tid - 32;
        float v = 0.f;
        for (int i = lid; i < vlen; i += 32) {
            const float vv = __ldg(&V[i]);
            v = fmaf(vv, vv, v);
        }
        #pragma unroll
        for (int off = 16; off; off >>= 1)
            v += __shfl_down_sync(0xFFFFFFFFu, v, off);
        if (lid == 0) scoef[4] = v;
    } else if (tid == 64) {
        scoef[5] = __ldg(a);
    }
    __syncthreads();

    const float c0 = scoef[0], c1 = scoef[1], c2 = scoef[2], c3 = scoef[3];
    const float lin = scoef[4], av = scoef[5];
    const bool wb_nonneg = (sneg == 0);

    // ---- Phase 3: evaluate one float4 of t per thread ----
    float m   = __int_as_float(INF_BITS);
    bool  bad = false;   // slow path used (needs exact min machinery)
    if (have_t) {
        float4 o;
        #pragma unroll
        for (int j = 0; j < 4; ++j) {
            const float tv = (&tv4.x)[j];
            float v;
            if (wb_nonneg && tv >= 0.f) {
                // exact: relu is identity on this element's whole z-column
                v = av + fmaf(lin, tv,
                        fmaf(fmaf(fmaf(c3, tv, c2), tv, c1), tv, c0));
            } else {
                bad = true;
                // exact fallback: brute-force relu network for this element
                float nn = 0.f;
                for (int k = 0; k < KU; ++k) {
                    float prim = 0.f, gate = 0.f;
                    #pragma unroll 8
                    for (int n = 0; n < NU; ++n) {
                        const float wv = __ldg(&W[k * NU + n]);
                        const float bv = __ldg(&b[k * NU + n]);
                        const float r  = fmaxf(fmaf(wv, tv, bv), 0.f);
                        prim = fmaf(r, r, prim);
                        gate = fmaf(wv, r, gate);
                    }
                    nn = fmaf(0.5f * prim, gate, nn);
                }
                v = av + fmaf(lin, tv, nn);
            }
            (&o.x)[j] = v;
            m = fminf(m, v);
        }
        ((float4*)out)[i4] = o;
    }
    // scalar tail (T not multiple of 4) handled by block 0
    if (blockIdx.x == 0 && tid < tail) {
        const int i = (T4 << 2) + tid;
        const float tv = t[i];
        float v;
        if (wb_nonneg && tv >= 0.f) {
            v = av + fmaf(lin, tv, fmaf(fmaf(fmaf(c3, tv, c2), tv, c1), tv, c0));
        } else {
            bad = true;
            float nn = 0.f;
            for (int k = 0; k < KU; ++k) {
                float prim = 0.f, gate = 0.f;
                for (int n = 0; n < NU; ++n) {
                    const float wv = __ldg(&W[k * NU + n]);
                    const float bv = __ldg(&b[k * NU + n]);
                    const float r  = fmaxf(fmaf(wv, tv, bv), 0.f);
                    prim = fmaf(r, r, prim);
                    gate = fmaf(wv, r, gate);
                }
                nn = fmaf(0.5f * prim, gate, nn);
            }
            v = av + fmaf(lin, tv, nn);
        }
        out[i] = v;
        m = fminf(m, v);
    }

    // ---- Phase 4: block min; minimal tail ----
    #pragma unroll
    for (int off = 16; off; off >>= 1)
        m = fminf(m, __shfl_xor_sync(0xFFFFFFFFu, m, off));
    const unsigned wbad = __ballot_sync(0xFFFFFFFFu, bad);
    if ((tid & 31) == 0) { swm[tid >> 5] = m; sbad[tid >> 5] = (wbad != 0); }
    __syncthreads();   // tid 0 must see swm/sbad; also orders smem before exit

    if (tid != 0) return;   // everyone else is done — shortest possible tail

    // ---- Thread 0 only: escalate if needed, retire, maybe correct ----
    float bm = swm[0];
    int   anybad = sbad[0];
    #pragma unroll
    for (int w = 1; w < 8; ++w) { bm = fminf(bm, swm[w]); anybad |= sbad[w]; }

    // A block with min > 0 and no slow-path element cannot influence the
    // correction: if the global min <= 0 it lives in a block with min <= 0,
    // and if the global min > 0 the correction is 0 regardless.
    if (anybad || bm <= 0.f) {
        atomic_min_float(bm);
        atomicOr(&g_need, 1u);
    }

    // acq_rel RMW: releases this block's out-stores, acquires for the reads below
    const unsigned prev = retire_acq_rel(&g_done);
    if (prev == (unsigned)(nblocks - 1)) {
        // Last block. Correction is nonzero only if some block escalated.
        if (*((volatile unsigned*)&g_need) != 0u) {
            const float mn = __uint_as_float(*((volatile unsigned*)&g_min_bits));
            if (mn <= 0.f) {
                const float corr = EPSV - mn;
                // Rare path (never taken on this data): serial but correct.
                for (int i = 0; i < T; ++i) out[i] += corr;
            }
        }
        // restore invariants for the next graph replay
        g_need     = 0;
        g_min_bits = INF_BITS;
        __threadfence();
        g_done     = 0;
    }
}

// ---------------------------------------------------------------------------
extern "C" void kernel_launch(void* const* d_in, const int* in_sizes, int n_in,
                              void* d_out, int out_size) {
    const float* t = (const float*)d_in[0];
    const float* W = (const float*)d_in[1];
    const float* b = (const float*)d_in[2];
    const float* V = (const float*)d_in[3];
    const float* a = (const float*)d_in[4];
    float* out = (float*)d_out;

    const int T    = in_sizes[0];
    const int vlen = in_sizes[3];

    const int T4 = T >> 2;
    int nblocks = (T4 + 255) / 256;
    if (nblocks < 1) nblocks = 1;

    fused_mgn_kernel<<<nblocks, 256>>>(t, W, b, V, a, out, T, vlen, nblocks);
}

// round 6
// speedup vs baseline: 1.1429x; 1.1429x over previous
#include <cuda_runtime.h>
#include <cstdint>

// Shapes fixed by the reference: K=64, N=128, T=32768
#define KU   64
#define NU   128
#define EPSV 0.01f
#define INF_BITS 0x7F800000u

// Packed retirement counter: low 32 bits = total retires (monotonic across
// graph replays; lastness tested modulo nblocks), high 32 bits = escalation
// count. Common path never resets it; the rare path (a block saw v<=0 or a
// slow-path element) resets it to 0 after applying the correction.
__device__ unsigned long long g_state = 0ull;

__device__ __forceinline__ unsigned long long
retire_acq_rel(unsigned long long* ctr, unsigned long long enc) {
    unsigned long long prev;
    asm volatile("atom.acq_rel.gpu.global.add.u64 %0, [%1], %2;"
                 : "=l"(prev) : "l"(ctr), "l"(enc) : "memory");
    return prev;
}

// ---------------------------------------------------------------------------
// Single fused kernel. 256 threads/block, one float4 of t per thread.
// Every block redundantly derives the cubic coefficients from W,b (parallel
// across blocks). Common path: no numeric min, no fences, one packed ATOMG
// per block. Rare path (never on this data): last block serially recomputes
// the min from out[] and applies the positif shift.
// ---------------------------------------------------------------------------
__global__ void __launch_bounds__(256)
fused_mgn_kernel(const float* __restrict__ t,
                 const float* __restrict__ W,
                 const float* __restrict__ b,
                 const float* __restrict__ V,
                 const float* __restrict__ a,
                 float* __restrict__ out,
                 int T, int vlen, int nblocks) {
    __shared__ float4   swc[8];     // per-warp coefficient partials {c0,c1,c2,c3}
    __shared__ unsigned sneg[8];    // per-warp "saw negative W/b" (written unconditionally)
    __shared__ float    scoef[6];   // c0,c1,c2,c3,vsum,a
    __shared__ unsigned sflag[8];   // per-warp "needs correction machinery"

    const int tid  = threadIdx.x;
    const int wrp  = tid >> 5, lane = tid & 31;
    const int T4   = T >> 2;
    const int tail = T - (T4 << 2);
    const int i4   = blockIdx.x * 256 + tid;

    // ---- Hoisted t load: overlap its DRAM/L2 latency with the W/b loads ----
    float4 tv4 = make_float4(0.f, 0.f, 0.f, 0.f);
    const bool have_t = (i4 < T4);
    if (have_t) tv4 = __ldg(&((const float4*)t)[i4]);

    // ---- Phase 1: per-unit sums -> per-warp coefficient partials ----
    {
        // warp w owns units k = w*8 .. w*8+7; 4 lanes per unit.
        const int k = (wrp << 3) + (lane >> 2), quad = lane & 3;
        const float4* W4 = (const float4*)W;
        const float4* B4 = (const float4*)b;
        float s2 = 0.f, sb = 0.f, bb = 0.f;
        bool  neg = false;
        #pragma unroll
        for (int j = 0; j < 8; ++j) {              // 8 float4 = 32 floats each
            const int idx = k * (NU/4) + quad * 8 + j;
            const float4 w  = __ldg(&W4[idx]);
            const float4 bv = __ldg(&B4[idx]);
            #pragma unroll
            for (int c = 0; c < 4; ++c) {
                const float wv = (&w.x)[c], bvv = (&bv.x)[c];
                s2 = fmaf(wv,  wv,  s2);
                sb = fmaf(wv,  bvv, sb);
                bb = fmaf(bvv, bvv, bb);
                neg |= (wv < 0.f) | (bvv < 0.f);
            }
        }
        // reduce s2,sb,bb within each 4-lane unit group
        #pragma unroll
        for (int off = 2; off; off >>= 1) {
            s2 += __shfl_down_sync(0xFFFFFFFFu, s2, off, 4);
            sb += __shfl_down_sync(0xFFFFFFFFu, sb, off, 4);
            bb += __shfl_down_sync(0xFFFFFFFFu, bb, off, 4);
        }
        // per-unit cubic contributions (valid at quad==0 lanes; zero elsewhere)
        float c0, c1, c2, c3;
        if (quad == 0) {
            c3 = 0.5f * s2 * s2;
            c2 = 1.5f * s2 * sb;
            c1 = fmaf(sb, sb, 0.5f * bb * s2);
            c0 = 0.5f * bb * sb;
        } else {
            c0 = c1 = c2 = c3 = 0.f;
        }
        // warp-wide sum across the 8 units (nonzero lanes are 4 apart)
        #pragma unroll
        for (int off = 4; off <= 16; off <<= 1) {
            c0 += __shfl_xor_sync(0xFFFFFFFFu, c0, off);
            c1 += __shfl_xor_sync(0xFFFFFFFFu, c1, off);
            c2 += __shfl_xor_sync(0xFFFFFFFFu, c2, off);
            c3 += __shfl_xor_sync(0xFFFFFFFFu, c3, off);
        }
        const unsigned nb = __ballot_sync(0xFFFFFFFFu, neg);
        if (lane == 0) {
            swc[wrp]  = make_float4(c0, c1, c2, c3);
            sneg[wrp] = nb;                        // unconditional: no race
        }
    }
    __syncthreads();

    // ---- Phase 2: final reductions (parallel across warps) ----
    if (wrp == 0) {
        // transposed read: lane l holds partial coef (l&3) of warp (l>>2)
        float v = ((const float*)swc)[lane];
        #pragma unroll
        for (int off = 4; off <= 16; off <<= 1)
            v += __shfl_xor_sync(0xFFFFFFFFu, v, off);
        if (lane < 4) scoef[lane] = v;             // lanes 0..3 -> c0..c3
    } else if (wrp == 1) {
        // vsum = sum(V*V), vectorized
        const int v4n = vlen >> 2;
        float v = 0.f;
        for (int i = lane; i < v4n; i += 32) {
            const float4 vv = __ldg(&((const float4*)V)[i]);
            v = fmaf(vv.x, vv.x, fmaf(vv.y, vv.y, fmaf(vv.z, vv.z, vv.w * vv.w)));
        }
        for (int i = (v4n << 2) + lane; i < vlen; i += 32) {
            const float s = __ldg(&V[i]);
            v = fmaf(s, s, v);
        }
        #pragma unroll
        for (int off = 16; off; off >>= 1)
            v += __shfl_xor_sync(0xFFFFFFFFu, v, off);
        if (lane == 0) scoef[4] = v;
    } else if (tid == 64) {
        scoef[5] = __ldg(a);
    }
    __syncthreads();

    const float c0 = scoef[0], c1 = scoef[1], c2 = scoef[2], c3 = scoef[3];
    const float lin = scoef[4], av = scoef[5];
    const bool wb_nonneg = !(sneg[0] | sneg[1] | sneg[2] | sneg[3] |
                             sneg[4] | sneg[5] | sneg[6] | sneg[7]);

    // ---- Phase 3: evaluate one float4 of t per thread ----
    bool flag = false;   // this lane produced v<=0 or used the slow path
    if (have_t) {
        float4 o;
        #pragma unroll
        for (int j = 0; j < 4; ++j) {
            const float tv = (&tv4.x)[j];
            float v;
            if (wb_nonneg && tv >= 0.f) {
                // exact: relu is identity on this element's whole z-column
                v = av + fmaf(lin, tv,
                        fmaf(fmaf(fmaf(c3, tv, c2), tv, c1), tv, c0));
            } else {
                flag = true;
                // exact fallback: brute-force relu network for this element
                float nn = 0.f;
                for (int k = 0; k < KU; ++k) {
                    float prim = 0.f, gate = 0.f;
                    #pragma unroll 8
                    for (int n = 0; n < NU; ++n) {
                        const float wv = __ldg(&W[k * NU + n]);
                        const float bv = __ldg(&b[k * NU + n]);
                        const float r  = fmaxf(fmaf(wv, tv, bv), 0.f);
                        prim = fmaf(r, r, prim);
                        gate = fmaf(wv, r, gate);
                    }
                    nn = fmaf(0.5f * prim, gate, nn);
                }
                v = av + fmaf(lin, tv, nn);
            }
            flag |= (v <= 0.f);
            (&o.x)[j] = v;
        }
        ((float4*)out)[i4] = o;
    }
    // scalar tail (T not multiple of 4) handled by block 0
    if (blockIdx.x == 0 && tid < tail) {
        const int i = (T4 << 2) + tid;
        const float tv = t[i];
        float v;
        if (wb_nonneg && tv >= 0.f) {
            v = av + fmaf(lin, tv, fmaf(fmaf(fmaf(c3, tv, c2), tv, c1), tv, c0));
        } else {
            flag = true;
            float nn = 0.f;
            for (int k = 0; k < KU; ++k) {
                float prim = 0.f, gate = 0.f;
                for (int n = 0; n < NU; ++n) {
                    const float wv = __ldg(&W[k * NU + n]);
                    const float bv = __ldg(&b[k * NU + n]);
                    const float r  = fmaxf(fmaf(wv, tv, bv), 0.f);
                    prim = fmaf(r, r, prim);
                    gate = fmaf(wv, r, gate);
                }
                nn = fmaf(0.5f * prim, gate, nn);
            }
            v = av + fmaf(lin, tv, nn);
        }
        flag |= (v <= 0.f);
        out[i] = v;
    }

    // ---- Phase 4: flag-only epilogue (no numeric min on the common path) ----
    const unsigned wflag = __ballot_sync(0xFFFFFFFFu, flag);
    if (lane == 0) sflag[wrp] = wflag;
    __syncthreads();     // tid0 must see sflag; orders smem before exit

    if (tid != 0) return;

    const unsigned anyflag = sflag[0] | sflag[1] | sflag[2] | sflag[3] |
                             sflag[4] | sflag[5] | sflag[6] | sflag[7];

    // One packed acq_rel RMW: releases this block's out-stores; the last
    // block's RMW acquires, covering its out[] reads on the rare path.
    const unsigned long long enc = 1ull | (anyflag ? (1ull << 32) : 0ull);
    const unsigned long long prev = retire_acq_rel(&g_state, enc);

    const unsigned count = (unsigned)prev;               // retires so far (monotonic)
    if ((count % (unsigned)nblocks) != (unsigned)(nblocks - 1)) return;

    const bool need = ((prev >> 32) != 0ull) || anyflag;
    if (!need) return;                                   // common path: done

    // ---- Rare path: recompute exact min from out[], apply shift, reset ----
    float mn = __int_as_float(INF_BITS);
    for (int i = 0; i < T; ++i) mn = fminf(mn, out[i]);
    if (mn <= 0.f) {
        const float corr = EPSV - mn;
        for (int i = 0; i < T; ++i) out[i] += corr;
    }
    g_state = 0ull;      // clean slate for the next replay (stream-ordered)
}

// ---------------------------------------------------------------------------
extern "C" void kernel_launch(void* const* d_in, const int* in_sizes, int n_in,
                              void* d_out, int out_size) {
    const float* t = (const float*)d_in[0];
    const float* W = (const float*)d_in[1];
    const float* b = (const float*)d_in[2];
    const float* V = (const float*)d_in[3];
    const float* a = (const float*)d_in[4];
    float* out = (float*)d_out;

    const int T    = in_sizes[0];
    const int vlen = in_sizes[3];

    const int T4 = T >> 2;
    int nblocks = (T4 + 255) / 256;
    if (nblocks < 1) nblocks = 1;

    fused_mgn_kernel<<<nblocks, 256>>>(t, W, b, V, a, out, T, vlen, nblocks);
}

// round 7
// speedup vs baseline: 1.2647x; 1.1066x over previous
#include <cuda_runtime.h>
#include <cstdint>

// Shapes fixed by the reference: K=64, N=128, T=32768
#define KU   64
#define NU   128
#define EPSV 0.01f
#define INF_BITS 0x7F800000u

// Monotonic warp-retirement counter (8 warps per block). Never reset: a
// replay is complete exactly when count % (nblocks*8) == 0, and since
// (nblocks*8)=256 divides 2^32, u32 wraparound preserves the modulus.
__device__ unsigned int g_retire = 0u;

__device__ __forceinline__ void retire_release(unsigned int* ctr) {
    asm volatile("red.release.gpu.global.add.u32 [%0], 1;"
                 :: "l"(ctr) : "memory");
}
__device__ __forceinline__ unsigned load_acquire(const unsigned int* ctr) {
    unsigned v;
    asm volatile("ld.acquire.gpu.global.u32 %0, [%1];" : "=r"(v) : "l"(ctr));
    return v;
}

// ---------------------------------------------------------------------------
// Single fused kernel. 256 threads/block, one float4 of t per thread.
// Every block redundantly derives the cubic coefficients from W,b (parallel
// across blocks, identical order => bit-identical results in every block).
// Common-path epilogue per warp: ballot + syncwarp + ONE fire-and-forget
// release-RED by lane0, then exit. No block barrier, no atomic round-trip.
// Rare path (some element <= 0 or slow-path used): the lowest flagged lane
// of each flagged warp spins until all warps retired, then recomputes every
// element from inputs (bit-identical across fixers => benign write races),
// derives the exact min and rewrites out with the positif shift.
// ---------------------------------------------------------------------------
__global__ void __launch_bounds__(256)
fused_mgn_kernel(const float* __restrict__ t,
                 const float* __restrict__ W,
                 const float* __restrict__ b,
                 const float* __restrict__ V,
                 const float* __restrict__ a,
                 float* __restrict__ out,
                 int T, int vlen, int nblocks) {
    __shared__ float4   swc[8];     // per-warp coefficient partials {c0,c1,c2,c3}
    __shared__ unsigned sneg[8];    // per-warp "saw negative W/b" (unconditional write)
    __shared__ float    scoef[6];   // c0,c1,c2,c3,vsum,a

    const int tid  = threadIdx.x;
    const int wrp  = tid >> 5, lane = tid & 31;
    const int T4   = T >> 2;
    const int tail = T - (T4 << 2);
    const int i4   = blockIdx.x * 256 + tid;

    // ---- Hoisted t load: overlap its DRAM/L2 latency with the W/b loads ----
    float4 tv4 = make_float4(0.f, 0.f, 0.f, 0.f);
    const bool have_t = (i4 < T4);
    if (have_t) tv4 = __ldg(&((const float4*)t)[i4]);

    // ---- Phase 1: per-unit sums -> per-warp coefficient partials ----
    {
        // warp w owns units k = w*8 .. w*8+7; 4 lanes per unit.
        const int k = (wrp << 3) + (lane >> 2), quad = lane & 3;
        const float4* W4 = (const float4*)W;
        const float4* B4 = (const float4*)b;
        float s2 = 0.f, sb = 0.f, bb = 0.f;
        bool  neg = false;
        #pragma unroll
        for (int j = 0; j < 8; ++j) {              // 8 float4 = 32 floats each
            const int idx = k * (NU/4) + quad * 8 + j;
            const float4 w  = __ldg(&W4[idx]);
            const float4 bv = __ldg(&B4[idx]);
            #pragma unroll
            for (int c = 0; c < 4; ++c) {
                const float wv = (&w.x)[c], bvv = (&bv.x)[c];
                s2 = fmaf(wv,  wv,  s2);
                sb = fmaf(wv,  bvv, sb);
                bb = fmaf(bvv, bvv, bb);
                neg |= (wv < 0.f) | (bvv < 0.f);
            }
        }
        // reduce s2,sb,bb within each 4-lane unit group
        #pragma unroll
        for (int off = 2; off; off >>= 1) {
            s2 += __shfl_down_sync(0xFFFFFFFFu, s2, off, 4);
            sb += __shfl_down_sync(0xFFFFFFFFu, sb, off, 4);
            bb += __shfl_down_sync(0xFFFFFFFFu, bb, off, 4);
        }
        // per-unit cubic contributions (valid at quad==0 lanes; zero elsewhere)
        float c0, c1, c2, c3;
        if (quad == 0) {
            c3 = 0.5f * s2 * s2;
            c2 = 1.5f * s2 * sb;
            c1 = fmaf(sb, sb, 0.5f * bb * s2);
            c0 = 0.5f * bb * sb;
        } else {
            c0 = c1 = c2 = c3 = 0.f;
        }
        // warp-wide sum across the 8 units (nonzero lanes are 4 apart)
        #pragma unroll
        for (int off = 4; off <= 16; off <<= 1) {
            c0 += __shfl_xor_sync(0xFFFFFFFFu, c0, off);
            c1 += __shfl_xor_sync(0xFFFFFFFFu, c1, off);
            c2 += __shfl_xor_sync(0xFFFFFFFFu, c2, off);
            c3 += __shfl_xor_sync(0xFFFFFFFFu, c3, off);
        }
        const unsigned nb = __ballot_sync(0xFFFFFFFFu, neg);
        if (lane == 0) {
            swc[wrp]  = make_float4(c0, c1, c2, c3);
            sneg[wrp] = nb;                        // unconditional: no race
        }
    }
    __syncthreads();

    // ---- Phase 2: final reductions (parallel across warps) ----
    if (wrp == 0) {
        // transposed read: lane l holds partial coef (l&3) of warp (l>>2)
        float v = ((const float*)swc)[lane];
        #pragma unroll
        for (int off = 4; off <= 16; off <<= 1)
            v += __shfl_xor_sync(0xFFFFFFFFu, v, off);
        if (lane < 4) scoef[lane] = v;             // lanes 0..3 -> c0..c3
    } else if (wrp == 1) {
        // vsum = sum(V*V), vectorized
        const int v4n = vlen >> 2;
        float v = 0.f;
        for (int i = lane; i < v4n; i += 32) {
            const float4 vv = __ldg(&((const float4*)V)[i]);
            v = fmaf(vv.x, vv.x, fmaf(vv.y, vv.y, fmaf(vv.z, vv.z, vv.w * vv.w)));
        }
        for (int i = (v4n << 2) + lane; i < vlen; i += 32) {
            const float s = __ldg(&V[i]);
            v = fmaf(s, s, v);
        }
        #pragma unroll
        for (int off = 16; off; off >>= 1)
            v += __shfl_xor_sync(0xFFFFFFFFu, v, off);
        if (lane == 0) scoef[4] = v;
    } else if (tid == 64) {
        scoef[5] = __ldg(a);
    }
    __syncthreads();

    const float c0 = scoef[0], c1 = scoef[1], c2 = scoef[2], c3 = scoef[3];
    const float lin = scoef[4], av = scoef[5];
    const bool wb_nonneg = !(sneg[0] | sneg[1] | sneg[2] | sneg[3] |
                             sneg[4] | sneg[5] | sneg[6] | sneg[7]);

    // ---- Phase 3: evaluate one float4 of t per thread ----
    bool flag = false;   // this lane produced v<=0 or used the slow path
    if (have_t) {
        float4 o;
        #pragma unroll
        for (int j = 0; j < 4; ++j) {
            const float tv = (&tv4.x)[j];
            float v;
            if (wb_nonneg && tv >= 0.f) {
                // exact: relu is identity on this element's whole z-column
                v = av + fmaf(lin, tv,
                        fmaf(fmaf(fmaf(c3, tv, c2), tv, c1), tv, c0));
            } else {
                flag = true;
                // exact fallback: brute-force relu network for this element
                float nn = 0.f;
                for (int k = 0; k < KU; ++k) {
                    float prim = 0.f, gate = 0.f;
                    #pragma unroll 8
                    for (int n = 0; n < NU; ++n) {
                        const float wv = __ldg(&W[k * NU + n]);
                        const float bv = __ldg(&b[k * NU + n]);
                        const float r  = fmaxf(fmaf(wv, tv, bv), 0.f);
                        prim = fmaf(r, r, prim);
                        gate = fmaf(wv, r, gate);
                    }
                    nn = fmaf(0.5f * prim, gate, nn);
                }
                v = av + fmaf(lin, tv, nn);
            }
            flag |= (v <= 0.f);
            (&o.x)[j] = v;
        }
        ((float4*)out)[i4] = o;
    }
    // scalar tail (T not multiple of 4) handled by block 0
    if (blockIdx.x == 0 && tid < tail) {
        const int i = (T4 << 2) + tid;
        const float tv = t[i];
        float v;
        if (wb_nonneg && tv >= 0.f) {
            v = av + fmaf(lin, tv, fmaf(fmaf(fmaf(c3, tv, c2), tv, c1), tv, c0));
        } else {
            flag = true;
            float nn = 0.f;
            for (int k = 0; k < KU; ++k) {
                float prim = 0.f, gate = 0.f;
                for (int n = 0; n < NU; ++n) {
                    const float wv = __ldg(&W[k * NU + n]);
                    const float bv = __ldg(&b[k * NU + n]);
                    const float r  = fmaxf(fmaf(wv, tv, bv), 0.f);
                    prim = fmaf(r, r, prim);
                    gate = fmaf(wv, r, gate);
                }
                nn = fmaf(0.5f * prim, gate, nn);
            }
            v = av + fmaf(lin, tv, nn);
        }
        flag |= (v <= 0.f);
        out[i] = v;
    }

    // ---- Epilogue: per-warp fire-and-forget retire; no block barrier ----
    const unsigned wflag = __ballot_sync(0xFFFFFFFFu, flag);
    __syncwarp();   // warp-scope ordering: lanes' STGs happen-before lane0's RED
    if (lane == 0) retire_release(&g_retire);
    if (wflag == 0) return;                 // common path: warp exits, no waits

    // ---- Rare path: lowest flagged lane of this warp becomes a fixer ----
    if (lane != (__ffs(wflag) - 1)) return;

    const unsigned M = (unsigned)nblocks * 8u;     // warp retires per replay
    unsigned c;
    do { c = load_acquire(&g_retire); } while ((c % M) != 0u);

    // Recompute every element from inputs (identical ops => identical bits in
    // every fixer => concurrent same-value writes are benign), find the exact
    // min, then rewrite out with the positif shift.
    float mn = __int_as_float(INF_BITS);
    for (int i = 0; i < T; ++i) {
        const float tv = t[i];
        float v;
        if (wb_nonneg && tv >= 0.f) {
            v = av + fmaf(lin, tv, fmaf(fmaf(fmaf(c3, tv, c2), tv, c1), tv, c0));
        } else {
            float nn = 0.f;
            for (int k = 0; k < KU; ++k) {
                float prim = 0.f, gate = 0.f;
                for (int n = 0; n < NU; ++n) {
                    const float wv = __ldg(&W[k * NU + n]);
                    const float bv = __ldg(&b[k * NU + n]);
                    const float r  = fmaxf(fmaf(wv, tv, bv), 0.f);
                    prim = fmaf(r, r, prim);
                    gate = fmaf(wv, r, gate);
                }
                nn = fmaf(0.5f * prim, gate, nn);
            }
            v = av + fmaf(lin, tv, nn);
        }
        mn = fminf(mn, v);
    }
    if (mn <= 0.f) {
        const float corr = EPSV - mn;
        for (int i = 0; i < T; ++i) {
            const float tv = t[i];
            float v;
            if (wb_nonneg && tv >= 0.f) {
                v = av + fmaf(lin, tv, fmaf(fmaf(fmaf(c3, tv, c2), tv, c1), tv, c0));
            } else {
                float nn = 0.f;
                for (int k = 0; k < KU; ++k) {
                    float prim = 0.f, gate = 0.f;
                    for (int n = 0; n < NU; ++n) {
                        const float wv = __ldg(&W[k * NU + n]);
                        const float bv = __ldg(&b[k * NU + n]);
                        const float r  = fmaxf(fmaf(wv, tv, bv), 0.f);
                        prim = fmaf(r, r, prim);
                        gate = fmaf(wv, r, gate);
                    }
                    nn = fmaf(0.5f * prim, gate, nn);
                }
                v = av + fmaf(lin, tv, nn);
            }
            out[i] = v + corr;
        }
    }
}

// ---------------------------------------------------------------------------
extern "C" void kernel_launch(void* const* d_in, const int* in_sizes, int n_in,
                              void* d_out, int out_size) {
    const float* t = (const float*)d_in[0];
    const float* W = (const float*)d_in[1];
    const float* b = (const float*)d_in[2];
    const float* V = (const float*)d_in[3];
    const float* a = (const float*)d_in[4];
    float* out = (float*)d_out;

    const int T    = in_sizes[0];
    const int vlen = in_sizes[3];

    const int T4 = T >> 2;
    int nblocks = (T4 + 255) / 256;
    if (nblocks < 1) nblocks = 1;

    fused_mgn_kernel<<<nblocks, 256>>>(t, W, b, V, a, out, T, vlen, nblocks);
}